// round 5
// baseline (speedup 1.0000x reference)
#include <cuda_runtime.h>
#include <math.h>
#include <stdint.h>

#define B_ 256
#define S_ 512
#define E_ 1024
#define H_ 1024
#define O_ 512

// ---------------------------------------------------------------------------
// Device scratch
// NOTE: g_hsplit / g_wsplit planes are stored with a k-pair PERMUTATION along
// their last (H) dim: within each 8-col block, orig col j is stored at
// pos = ((j&3)<<1) | (j>>2).  This makes the mma fragment pairs (t, t+4)
// adjacent so the step kernel can use LDS.64.
// ---------------------------------------------------------------------------
__device__ float g_xp[S_ * B_ * H_];       // [S,B,H] input projections (plain)
__device__ float g_h[2][B_ * H_];          // full-precision h (plain layout)
__device__ float g_hsplit[4][B_ * H_];     // plane = buf*2 + part (hi/lo tf32, permuted)
__device__ float g_wsplit[2][H_ * H_];     // W_hh split hi/lo (permuted cols)

// ---------------------------------------------------------------------------
// Helpers
// ---------------------------------------------------------------------------
__device__ __forceinline__ uint32_t smem_u32(const void* p) {
    uint32_t a;
    asm("{ .reg .u64 t; cvta.to.shared.u64 t, %1; cvt.u32.u64 %0, t; }" : "=r"(a) : "l"(p));
    return a;
}
__device__ __forceinline__ float tf32_rna(float x) {
    uint32_t u; asm("cvt.rna.tf32.f32 %0, %1;" : "=r"(u) : "f"(x));
    return __uint_as_float(u);
}

#define CP_ASYNC16(dst, src) \
    asm volatile("cp.async.cg.shared.global [%0], [%1], 16;" :: "r"(dst), "l"(src))
#define CP_COMMIT() asm volatile("cp.async.commit_group;" ::: "memory")
#define CP_WAIT0()  asm volatile("cp.async.wait_group 0;" ::: "memory")
#define CP_WAIT1()  asm volatile("cp.async.wait_group 1;" ::: "memory")
#define CP_WAIT2()  asm volatile("cp.async.wait_group 2;" ::: "memory")

// D += A*B   (m16n8k8 tf32, row.col)
__device__ __forceinline__ void mma_tf32(float* c,
    uint32_t a0, uint32_t a1, uint32_t a2, uint32_t a3, uint32_t b0, uint32_t b1)
{
    asm volatile(
        "mma.sync.aligned.m16n8k8.row.col.f32.tf32.tf32.f32 "
        "{%0,%1,%2,%3}, {%4,%5,%6,%7}, {%8,%9}, {%0,%1,%2,%3};"
        : "+f"(c[0]), "+f"(c[1]), "+f"(c[2]), "+f"(c[3])
        : "r"(a0), "r"(a1), "r"(a2), "r"(a3), "r"(b0), "r"(b1));
}

// ---------------------------------------------------------------------------
// Recurrent step: h_out = tanh(h_in @ W_hh^T + xp_t + b_hh) via 3xTF32 mma.sync
// CTA tile M=32, N=64.  Grid (16, 8) = 128 CTAs, 256 threads (8 warps).
// Warp = (nslot in 2) x (kgrp in 4), warp tile m32 x n32 over K/4 = 256.
// 3-stage cp.async pipeline, BK=64 per stage.  XOR-swizzled smem, LDS.64 frags.
// ---------------------------------------------------------------------------
#define BK 64
#define A_PL (32 * 64)                  // floats per A plane per stage (2048)
#define B_PL (64 * 64)                  // floats per B plane per stage (4096)
#define STAGE_FLOATS (2 * A_PL + 2 * B_PL)   // 12288
#define NSTAGE 3
#define STEP_SMEM (NSTAGE * STAGE_FLOATS * 4)  // 147456 bytes
#define NIT (H_ / BK)                   // 16

// swizzled float index within a plane (row-major, 64 floats/row, 16B-chunk XOR)
__device__ __forceinline__ int swf(int row, int col) {
    return (row << 6) + ((((col >> 2) ^ (row & 7))) << 2) + (col & 3);
}

__device__ __forceinline__ void load_stage(
    uint32_t smBase, int stage,
    const float* __restrict__ ahi, const float* __restrict__ alo,
    const float* __restrict__ whi, const float* __restrict__ wlo,
    int k0, int mbase, int nbase, int tid)
{
    uint32_t s = smBase + stage * (STAGE_FLOATS * 4);
    // A planes: 32 rows x 16 chunks = 512 chunks -> 2 per thread
#pragma unroll
    for (int j = 0; j < 2; j++) {
        int idx = tid + j * 256;
        int row = idx >> 4, q = idx & 15;
        int qs = q ^ (row & 7);
        uint32_t doff = ((row << 6) + (qs << 2)) * 4;
        size_t soff = (size_t)(mbase + row) * H_ + k0 + q * 4;
        CP_ASYNC16(s + doff, ahi + soff);
        CP_ASYNC16(s + A_PL * 4 + doff, alo + soff);
    }
    // B planes: 64 rows x 16 chunks = 1024 chunks -> 4 per thread
#pragma unroll
    for (int j = 0; j < 4; j++) {
        int idx = tid + j * 256;
        int row = idx >> 4, q = idx & 15;
        int qs = q ^ (row & 7);
        uint32_t doff = ((row << 6) + (qs << 2)) * 4;
        size_t soff = (size_t)(nbase + row) * H_ + k0 + q * 4;
        CP_ASYNC16(s + 2 * A_PL * 4 + doff, whi + soff);
        CP_ASYNC16(s + 2 * A_PL * 4 + B_PL * 4 + doff, wlo + soff);
    }
    CP_COMMIT();
}

__global__ __launch_bounds__(256, 1) void rnn_step_kernel(
    const float* __restrict__ ahi, const float* __restrict__ alo,
    const float* __restrict__ whi, const float* __restrict__ wlo,
    const float* __restrict__ xp_t, const float* __restrict__ b_hh,
    float* __restrict__ hf_out, float* __restrict__ hhi_out,
    float* __restrict__ hlo_out)
{
    extern __shared__ float sm[];
    const int tid = threadIdx.x;
    const int wid = tid >> 5;
    const int lane = tid & 31;
    const int g = lane >> 2;       // groupID 0..7
    const int t = lane & 3;        // 0..3

    const int nslot = wid & 1;     // n half of CTA tile
    const int kgrp = wid >> 1;     // 0..3, K split

    const int nblk = blockIdx.x;   // 0..15
    const int mblk = blockIdx.y;   // 0..7
    const int mbase = mblk * 32;
    const int nbase = nblk * 64;
    const int nb0 = nslot * 32;

    uint32_t smBase = smem_u32(sm);

    float acc[2][4][4];
#pragma unroll
    for (int mt = 0; mt < 2; mt++)
#pragma unroll
        for (int nt = 0; nt < 4; nt++)
#pragma unroll
            for (int i = 0; i < 4; i++) acc[mt][nt][i] = 0.f;

    load_stage(smBase, 0, ahi, alo, whi, wlo, 0, mbase, nbase, tid);
    load_stage(smBase, 1, ahi, alo, whi, wlo, BK, mbase, nbase, tid);

    for (int it = 0; it < NIT; it++) {
        int stage = it % NSTAGE;
        if (it + 2 < NIT) {
            load_stage(smBase, (it + 2) % NSTAGE, ahi, alo, whi, wlo,
                       (it + 2) * BK, mbase, nbase, tid);
            CP_WAIT2();
        } else if (it + 1 < NIT) {
            CP_WAIT1();
        } else {
            CP_WAIT0();
        }
        __syncthreads();

        const float* Ah = sm + stage * STAGE_FLOATS;
        const float* Al = Ah + A_PL;
        const float* Bh = Ah + 2 * A_PL;
        const float* Bl = Bh + B_PL;

#pragma unroll
        for (int k8 = 0; k8 < 2; k8++) {
            const int kc = kgrp * 16 + k8 * 8;
            const int col = kc + 2 * t;
            // A fragments: rows mt*16 + rp*8 + g, pairs (a0,a2)/(a1,a3) via float2
            float2 fh[4], fl[4];
#pragma unroll
            for (int mt = 0; mt < 2; mt++)
#pragma unroll
                for (int rp = 0; rp < 2; rp++) {
                    int r = mt * 16 + rp * 8 + g;
                    fh[mt * 2 + rp] = *(const float2*)&Ah[swf(r, col)];
                    fl[mt * 2 + rp] = *(const float2*)&Al[swf(r, col)];
                }
#pragma unroll
            for (int nt = 0; nt < 4; nt++) {
                int nr = nb0 + nt * 8 + g;
                float2 bh = *(const float2*)&Bh[swf(nr, col)];
                float2 bl = *(const float2*)&Bl[swf(nr, col)];
                uint32_t bh0 = __float_as_uint(bh.x), bh1 = __float_as_uint(bh.y);
                uint32_t bl0 = __float_as_uint(bl.x), bl1 = __float_as_uint(bl.y);
#pragma unroll
                for (int mt = 0; mt < 2; mt++) {
                    uint32_t a0 = __float_as_uint(fh[mt * 2].x);
                    uint32_t a1 = __float_as_uint(fh[mt * 2 + 1].x);
                    uint32_t a2 = __float_as_uint(fh[mt * 2].y);
                    uint32_t a3 = __float_as_uint(fh[mt * 2 + 1].y);
                    uint32_t l0 = __float_as_uint(fl[mt * 2].x);
                    uint32_t l1 = __float_as_uint(fl[mt * 2 + 1].x);
                    uint32_t l2 = __float_as_uint(fl[mt * 2].y);
                    uint32_t l3 = __float_as_uint(fl[mt * 2 + 1].y);
                    mma_tf32(acc[mt][nt], a0, a1, a2, a3, bh0, bh1);
                    mma_tf32(acc[mt][nt], a0, a1, a2, a3, bl0, bl1);
                    mma_tf32(acc[mt][nt], l0, l1, l2, l3, bh0, bh1);
                }
            }
        }
        __syncthreads();
    }

    // ---------------- K-split reduction through smem ----------------
    float* red = sm;   // all cp.async drained; stages reusable
    if (kgrp > 0) {
        int base = ((kgrp - 1) * 2 + nslot) * 1024 + lane * 32;
#pragma unroll
        for (int ch = 0; ch < 8; ch++) {
            int mt = ch >> 2, nt = ch & 3;
            int chs = ch ^ (lane & 7);
            *(float4*)&red[base + chs * 4] = *(const float4*)acc[mt][nt];
        }
    }
    __syncthreads();
    if (kgrp == 0) {
#pragma unroll
        for (int k = 1; k < 4; k++) {
            int base = ((k - 1) * 2 + nslot) * 1024 + lane * 32;
#pragma unroll
            for (int ch = 0; ch < 8; ch++) {
                int mt = ch >> 2, nt = ch & 3;
                int chs = ch ^ (lane & 7);
                float4 v = *(const float4*)&red[base + chs * 4];
                acc[mt][nt][0] += v.x; acc[mt][nt][1] += v.y;
                acc[mt][nt][2] += v.z; acc[mt][nt][3] += v.w;
            }
        }

        // ---------------- epilogue: + xp + b_hh, tanh, store planes ----------
#pragma unroll
        for (int mt = 0; mt < 2; mt++) {
            const int row0 = mbase + mt * 16 + g;
            const int row1 = row0 + 8;
#pragma unroll
            for (int nt = 0; nt < 4; nt++) {
                const int jb = nbase + nb0 + nt * 8;
                const int col = jb + 2 * t;
                float2 bv = *(const float2*)(b_hh + col);
                float2 x0 = *(const float2*)(xp_t + (size_t)row0 * H_ + col);
                float2 x1 = *(const float2*)(xp_t + (size_t)row1 * H_ + col);

                float v0 = tanhf(acc[mt][nt][0] + x0.x + bv.x);
                float v1 = tanhf(acc[mt][nt][1] + x0.y + bv.y);
                float v2 = tanhf(acc[mt][nt][2] + x1.x + bv.x);
                float v3 = tanhf(acc[mt][nt][3] + x1.y + bv.y);

                float h0 = tf32_rna(v0), h1 = tf32_rna(v1);
                float h2 = tf32_rna(v2), h3 = tf32_rna(v3);

                // plain layout for classifier / debugging
                *(float2*)(hf_out + (size_t)row0 * H_ + col) = make_float2(v0, v1);
                *(float2*)(hf_out + (size_t)row1 * H_ + col) = make_float2(v2, v3);

                // permuted positions for next step's MMA operands
                const int p0 = jb + (((2 * t) & 3) << 1) + (t >> 1);
                const int p1 = jb + (((2 * t + 1) & 3) << 1) + (t >> 1);
                hhi_out[(size_t)row0 * H_ + p0] = h0;
                hhi_out[(size_t)row0 * H_ + p1] = h1;
                hhi_out[(size_t)row1 * H_ + p0] = h2;
                hhi_out[(size_t)row1 * H_ + p1] = h3;
                hlo_out[(size_t)row0 * H_ + p0] = tf32_rna(v0 - h0);
                hlo_out[(size_t)row0 * H_ + p1] = tf32_rna(v1 - h1);
                hlo_out[(size_t)row1 * H_ + p0] = tf32_rna(v2 - h2);
                hlo_out[(size_t)row1 * H_ + p1] = tf32_rna(v3 - h3);
            }
        }
    }
}

// ---------------------------------------------------------------------------
// Kernel 1: fused embedding gather + input projection (scalar SGEMM)
// ---------------------------------------------------------------------------
__global__ __launch_bounds__(256) void embed_proj_kernel(
    const int* __restrict__ x, const float* __restrict__ emb,
    const float* __restrict__ W_ih, const float* __restrict__ b_ih)
{
    __shared__ float As[16][132];
    __shared__ float Bs[16][132];
    __shared__ int tok_s[128];

    const int tid  = threadIdx.x;
    const int brow = blockIdx.y;
    const int bcol = blockIdx.x;

    if (tid < 128) {
        int r = brow * 128 + tid;
        int s = r / B_;
        int b = r % B_;
        tok_s[tid] = x[b * S_ + s];
    }
    __syncthreads();

    const int ty = tid >> 4;
    const int tx = tid & 15;

    float acc[8][8];
#pragma unroll
    for (int i = 0; i < 8; i++)
#pragma unroll
        for (int j = 0; j < 8; j++) acc[i][j] = 0.f;

    for (int k0 = 0; k0 < E_; k0 += 16) {
#pragma unroll
        for (int l = 0; l < 2; l++) {
            int vid = tid + l * 256;
            int m = vid >> 2;
            int q = vid & 3;
            float4 a = *(const float4*)(emb + (size_t)tok_s[m] * E_ + k0 + q * 4);
            As[q * 4 + 0][m] = a.x; As[q * 4 + 1][m] = a.y;
            As[q * 4 + 2][m] = a.z; As[q * 4 + 3][m] = a.w;
            float4 w = *(const float4*)(W_ih + (size_t)(bcol * 128 + m) * E_ + k0 + q * 4);
            Bs[q * 4 + 0][m] = w.x; Bs[q * 4 + 1][m] = w.y;
            Bs[q * 4 + 2][m] = w.z; Bs[q * 4 + 3][m] = w.w;
        }
        __syncthreads();

#pragma unroll
        for (int kk = 0; kk < 16; kk++) {
            float ra[8], rb[8];
#pragma unroll
            for (int i = 0; i < 8; i++) ra[i] = As[kk][ty * 8 + i];
#pragma unroll
            for (int j = 0; j < 8; j++) rb[j] = Bs[kk][tx * 8 + j];
#pragma unroll
            for (int i = 0; i < 8; i++)
#pragma unroll
                for (int j = 0; j < 8; j++) acc[i][j] += ra[i] * rb[j];
        }
        __syncthreads();
    }

#pragma unroll
    for (int i = 0; i < 8; i++) {
        int r = brow * 128 + ty * 8 + i;
        float* dst = g_xp + (size_t)r * H_ + bcol * 128 + tx * 8;
        int colb = bcol * 128 + tx * 8;
#pragma unroll
        for (int j = 0; j < 8; j++)
            dst[j] = acc[i][j] + b_ih[colb + j];
    }
}

// ---------------------------------------------------------------------------
// Classifier GEMM (scalar, tiny)
// ---------------------------------------------------------------------------
__global__ __launch_bounds__(256) void gemm_clf(
    const float* __restrict__ A, const float* __restrict__ W,
    const float* __restrict__ bias, float* __restrict__ C, int N, int K)
{
    __shared__ float As[16][36];
    __shared__ float Bs[16][68];

    const int tid = threadIdx.x;
    const int rowBase = blockIdx.y * 32;
    const int colBase = blockIdx.x * 64;
    const int tr = tid >> 5;
    const int tc = tid & 31;

    float acc[4][2];
#pragma unroll
    for (int i = 0; i < 4; i++) { acc[i][0] = 0.f; acc[i][1] = 0.f; }

    for (int k0 = 0; k0 < K; k0 += 16) {
        if (tid < 128) {
            int m = tid >> 2, q = tid & 3;
            float4 a = *(const float4*)(A + (size_t)(rowBase + m) * K + k0 + q * 4);
            As[q * 4 + 0][m] = a.x; As[q * 4 + 1][m] = a.y;
            As[q * 4 + 2][m] = a.z; As[q * 4 + 3][m] = a.w;
        }
        {
            int n = tid >> 2, q = tid & 3;
            float4 w = *(const float4*)(W + (size_t)(colBase + n) * K + k0 + q * 4);
            Bs[q * 4 + 0][n] = w.x; Bs[q * 4 + 1][n] = w.y;
            Bs[q * 4 + 2][n] = w.z; Bs[q * 4 + 3][n] = w.w;
        }
        __syncthreads();

#pragma unroll
        for (int kk = 0; kk < 16; kk++) {
            float ra[4], rb[2];
#pragma unroll
            for (int i = 0; i < 4; i++) ra[i] = As[kk][tr * 4 + i];
            rb[0] = Bs[kk][tc * 2 + 0];
            rb[1] = Bs[kk][tc * 2 + 1];
#pragma unroll
            for (int i = 0; i < 4; i++) {
                acc[i][0] += ra[i] * rb[0];
                acc[i][1] += ra[i] * rb[1];
            }
        }
        __syncthreads();
    }

#pragma unroll
    for (int i = 0; i < 4; i++) {
        int row = rowBase + tr * 4 + i;
#pragma unroll
        for (int j = 0; j < 2; j++) {
            int col = colBase + tc * 2 + j;
            C[(size_t)row * N + col] = acc[i][j] + bias[col];
        }
    }
}

// ---------------------------------------------------------------------------
// Init kernels
// ---------------------------------------------------------------------------
__global__ void zero_h_kernel() {
    int i = blockIdx.x * blockDim.x + threadIdx.x;
    if (i < B_ * H_) {
        g_h[0][i] = 0.f;
        g_hsplit[0][i] = 0.f;
        g_hsplit[1][i] = 0.f;
    }
}

__global__ void wsplit_kernel(const float* __restrict__ W) {
    int i = blockIdx.x * blockDim.x + threadIdx.x;
    if (i < H_ * H_) {
        int row = i >> 10;
        int col = i & 1023;
        int j = col & 7;
        int p = (col & ~7) | ((j & 3) << 1) | (j >> 2);   // k-pair permutation
        float w = W[i];
        float hi = tf32_rna(w);
        g_wsplit[0][(size_t)row * H_ + p] = hi;
        g_wsplit[1][(size_t)row * H_ + p] = tf32_rna(w - hi);
    }
}

// ---------------------------------------------------------------------------
extern "C" void kernel_launch(void* const* d_in, const int* in_sizes, int n_in,
                              void* d_out, int out_size)
{
    const int*   x     = (const int*)d_in[0];
    const float* emb   = (const float*)d_in[1];
    const float* W_ih  = (const float*)d_in[2];
    const float* b_ih  = (const float*)d_in[3];
    const float* W_hh  = (const float*)d_in[4];
    const float* b_hh  = (const float*)d_in[5];
    const float* W_clf = (const float*)d_in[6];
    const float* b_clf = (const float*)d_in[7];
    float*       out   = (float*)d_out;

    float *xp = nullptr, *hb = nullptr, *hs = nullptr, *ws = nullptr;
    cudaGetSymbolAddress((void**)&xp, g_xp);
    cudaGetSymbolAddress((void**)&hb, g_h);
    cudaGetSymbolAddress((void**)&hs, g_hsplit);
    cudaGetSymbolAddress((void**)&ws, g_wsplit);

    static bool attrSet = false;
    if (!attrSet) {
        cudaFuncSetAttribute(rnn_step_kernel,
                             cudaFuncAttributeMaxDynamicSharedMemorySize, STEP_SMEM);
        attrSet = true;
    }

    // --- init: h0 = 0, split W_hh into permuted hi/lo tf32 planes ---
    zero_h_kernel<<<(B_ * H_ + 255) / 256, 256>>>();
    wsplit_kernel<<<(H_ * H_ + 255) / 256, 256>>>(W_hh);

    // --- xp[s,b,h] = emb[x[b,s]] @ W_ih^T + b_ih ---
    embed_proj_kernel<<<dim3(H_ / 128, (B_ * S_) / 128), 256>>>(x, emb, W_ih, b_ih);

    // --- scan: h_{t+1} = tanh(h_t @ W_hh^T + xp_t + b_hh) ---
    const float* whi = ws;
    const float* wlo = ws + (size_t)H_ * H_;
    for (int s = 0; s < S_; s++) {
        int in_buf = s & 1;
        int out_buf = (s + 1) & 1;
        const float* xpt = xp + (size_t)s * B_ * H_;
        rnn_step_kernel<<<dim3(16, 8), 256, STEP_SMEM>>>(
            hs + (size_t)(in_buf * 2) * B_ * H_,
            hs + (size_t)(in_buf * 2 + 1) * B_ * H_,
            whi, wlo, xpt, b_hh,
            hb + (size_t)out_buf * B_ * H_,
            hs + (size_t)(out_buf * 2) * B_ * H_,
            hs + (size_t)(out_buf * 2 + 1) * B_ * H_);
    }

    // --- classifier: out = h_final @ W_clf^T + b_clf (final in buffer 0) ---
    gemm_clf<<<dim3(O_ / 64, B_ / 32), 256>>>(hb, W_clf, b_clf, out, O_, H_);
}

// round 6
// speedup vs baseline: 1.0010x; 1.0010x over previous
#include <cuda_runtime.h>
#include <math.h>
#include <stdint.h>

#define B_ 256
#define S_ 512
#define E_ 1024
#define H_ 1024
#define O_ 512

// ---------------------------------------------------------------------------
// Device scratch
// NOTE: g_hsplit / g_wsplit planes are stored with a k-pair PERMUTATION along
// their last (H) dim: within each 8-col block, orig col j is stored at
// pos = ((j&3)<<1) | (j>>2).  This makes the mma fragment pairs (t, t+4)
// adjacent so the step kernel can use LDS.64.
// ---------------------------------------------------------------------------
__device__ float g_xp[S_ * B_ * H_];       // [S,B,H] input projections (plain)
__device__ float g_h[2][B_ * H_];          // full-precision h (plain layout)
__device__ float g_hsplit[4][B_ * H_];     // plane = buf*2 + part (hi/lo tf32, permuted)
__device__ float g_wsplit[2][H_ * H_];     // W_hh split hi/lo (permuted cols)

// ---------------------------------------------------------------------------
// Helpers
// ---------------------------------------------------------------------------
__device__ __forceinline__ uint32_t smem_u32(const void* p) {
    uint32_t a;
    asm("{ .reg .u64 t; cvta.to.shared.u64 t, %1; cvt.u32.u64 %0, t; }" : "=r"(a) : "l"(p));
    return a;
}
__device__ __forceinline__ float tf32_rna(float x) {
    uint32_t u; asm("cvt.rna.tf32.f32 %0, %1;" : "=r"(u) : "f"(x));
    return __uint_as_float(u);
}

#define CP_ASYNC16(dst, src) \
    asm volatile("cp.async.cg.shared.global [%0], [%1], 16;" :: "r"(dst), "l"(src))
#define CP_COMMIT() asm volatile("cp.async.commit_group;" ::: "memory")
#define CP_WAIT0()  asm volatile("cp.async.wait_group 0;" ::: "memory")
#define CP_WAIT1()  asm volatile("cp.async.wait_group 1;" ::: "memory")
#define CP_WAIT2()  asm volatile("cp.async.wait_group 2;" ::: "memory")

// D += A*B   (m16n8k8 tf32, row.col)
__device__ __forceinline__ void mma_tf32(float* c,
    uint32_t a0, uint32_t a1, uint32_t a2, uint32_t a3, uint32_t b0, uint32_t b1)
{
    asm volatile(
        "mma.sync.aligned.m16n8k8.row.col.f32.tf32.tf32.f32 "
        "{%0,%1,%2,%3}, {%4,%5,%6,%7}, {%8,%9}, {%0,%1,%2,%3};"
        : "+f"(c[0]), "+f"(c[1]), "+f"(c[2]), "+f"(c[3])
        : "r"(a0), "r"(a1), "r"(a2), "r"(a3), "r"(b0), "r"(b1));
}

// ---------------------------------------------------------------------------
// Recurrent step: h_out = tanh(h_in @ W_hh^T + xp_t + b_hh) via 3xTF32 mma.sync
// CTA tile M=32, N=64.  Grid (16, 8) = 128 CTAs, 256 threads (8 warps).
// Warp = (nslot in 2) x (kgrp in 4), warp tile m32 x n32 over K/4 = 256.
// 3-stage cp.async pipeline, BK=64 per stage.  XOR-swizzled smem, LDS.64 frags.
// ---------------------------------------------------------------------------
#define BK 64
#define A_PL (32 * 64)                  // floats per A plane per stage (2048)
#define B_PL (64 * 64)                  // floats per B plane per stage (4096)
#define STAGE_FLOATS (2 * A_PL + 2 * B_PL)   // 12288
#define NSTAGE 3
#define STEP_SMEM (NSTAGE * STAGE_FLOATS * 4)  // 147456 bytes
#define NIT (H_ / BK)                   // 16

// swizzled float index within a plane (row-major, 64 floats/row, 16B-chunk XOR)
__device__ __forceinline__ int swf(int row, int col) {
    return (row << 6) + ((((col >> 2) ^ (row & 7))) << 2) + (col & 3);
}

__device__ __forceinline__ void load_stage(
    uint32_t smBase, int stage,
    const float* __restrict__ ahi, const float* __restrict__ alo,
    const float* __restrict__ whi, const float* __restrict__ wlo,
    int k0, int mbase, int nbase, int tid)
{
    uint32_t s = smBase + stage * (STAGE_FLOATS * 4);
    // A planes: 32 rows x 16 chunks = 512 chunks -> 2 per thread
#pragma unroll
    for (int j = 0; j < 2; j++) {
        int idx = tid + j * 256;
        int row = idx >> 4, q = idx & 15;
        int qs = q ^ (row & 7);
        uint32_t doff = ((row << 6) + (qs << 2)) * 4;
        size_t soff = (size_t)(mbase + row) * H_ + k0 + q * 4;
        CP_ASYNC16(s + doff, ahi + soff);
        CP_ASYNC16(s + A_PL * 4 + doff, alo + soff);
    }
    // B planes: 64 rows x 16 chunks = 1024 chunks -> 4 per thread
#pragma unroll
    for (int j = 0; j < 4; j++) {
        int idx = tid + j * 256;
        int row = idx >> 4, q = idx & 15;
        int qs = q ^ (row & 7);
        uint32_t doff = ((row << 6) + (qs << 2)) * 4;
        size_t soff = (size_t)(nbase + row) * H_ + k0 + q * 4;
        CP_ASYNC16(s + 2 * A_PL * 4 + doff, whi + soff);
        CP_ASYNC16(s + 2 * A_PL * 4 + B_PL * 4 + doff, wlo + soff);
    }
    CP_COMMIT();
}

__global__ __launch_bounds__(256, 1) void rnn_step_kernel(
    const float* __restrict__ ahi, const float* __restrict__ alo,
    const float* __restrict__ whi, const float* __restrict__ wlo,
    const float* __restrict__ xp_t, const float* __restrict__ b_hh,
    float* __restrict__ hf_out, float* __restrict__ hhi_out,
    float* __restrict__ hlo_out)
{
    extern __shared__ float sm[];
    const int tid = threadIdx.x;
    const int wid = tid >> 5;
    const int lane = tid & 31;
    const int g = lane >> 2;       // groupID 0..7
    const int t = lane & 3;        // 0..3

    const int nslot = wid & 1;     // n half of CTA tile
    const int kgrp = wid >> 1;     // 0..3, K split

    const int nblk = blockIdx.x;   // 0..15
    const int mblk = blockIdx.y;   // 0..7
    const int mbase = mblk * 32;
    const int nbase = nblk * 64;
    const int nb0 = nslot * 32;

    uint32_t smBase = smem_u32(sm);

    float acc[2][4][4];
#pragma unroll
    for (int mt = 0; mt < 2; mt++)
#pragma unroll
        for (int nt = 0; nt < 4; nt++)
#pragma unroll
            for (int i = 0; i < 4; i++) acc[mt][nt][i] = 0.f;

    load_stage(smBase, 0, ahi, alo, whi, wlo, 0, mbase, nbase, tid);
    load_stage(smBase, 1, ahi, alo, whi, wlo, BK, mbase, nbase, tid);

    for (int it = 0; it < NIT; it++) {
        int stage = it % NSTAGE;
        if (it + 2 < NIT) {
            load_stage(smBase, (it + 2) % NSTAGE, ahi, alo, whi, wlo,
                       (it + 2) * BK, mbase, nbase, tid);
            CP_WAIT2();
        } else if (it + 1 < NIT) {
            CP_WAIT1();
        } else {
            CP_WAIT0();
        }
        __syncthreads();

        const float* Ah = sm + stage * STAGE_FLOATS;
        const float* Al = Ah + A_PL;
        const float* Bh = Ah + 2 * A_PL;
        const float* Bl = Bh + B_PL;

#pragma unroll
        for (int k8 = 0; k8 < 2; k8++) {
            const int kc = kgrp * 16 + k8 * 8;
            const int col = kc + 2 * t;
            // A fragments: rows mt*16 + rp*8 + g, pairs (a0,a2)/(a1,a3) via float2
            float2 fh[4], fl[4];
#pragma unroll
            for (int mt = 0; mt < 2; mt++)
#pragma unroll
                for (int rp = 0; rp < 2; rp++) {
                    int r = mt * 16 + rp * 8 + g;
                    fh[mt * 2 + rp] = *(const float2*)&Ah[swf(r, col)];
                    fl[mt * 2 + rp] = *(const float2*)&Al[swf(r, col)];
                }
#pragma unroll
            for (int nt = 0; nt < 4; nt++) {
                int nr = nb0 + nt * 8 + g;
                float2 bh = *(const float2*)&Bh[swf(nr, col)];
                float2 bl = *(const float2*)&Bl[swf(nr, col)];
                uint32_t bh0 = __float_as_uint(bh.x), bh1 = __float_as_uint(bh.y);
                uint32_t bl0 = __float_as_uint(bl.x), bl1 = __float_as_uint(bl.y);
#pragma unroll
                for (int mt = 0; mt < 2; mt++) {
                    uint32_t a0 = __float_as_uint(fh[mt * 2].x);
                    uint32_t a1 = __float_as_uint(fh[mt * 2 + 1].x);
                    uint32_t a2 = __float_as_uint(fh[mt * 2].y);
                    uint32_t a3 = __float_as_uint(fh[mt * 2 + 1].y);
                    uint32_t l0 = __float_as_uint(fl[mt * 2].x);
                    uint32_t l1 = __float_as_uint(fl[mt * 2 + 1].x);
                    uint32_t l2 = __float_as_uint(fl[mt * 2].y);
                    uint32_t l3 = __float_as_uint(fl[mt * 2 + 1].y);
                    mma_tf32(acc[mt][nt], a0, a1, a2, a3, bh0, bh1);
                    mma_tf32(acc[mt][nt], a0, a1, a2, a3, bl0, bl1);
                    mma_tf32(acc[mt][nt], l0, l1, l2, l3, bh0, bh1);
                }
            }
        }
        __syncthreads();
    }

    // ---------------- K-split reduction through smem ----------------
    float* red = sm;   // all cp.async drained; stages reusable
    if (kgrp > 0) {
        int base = ((kgrp - 1) * 2 + nslot) * 1024 + lane * 32;
#pragma unroll
        for (int ch = 0; ch < 8; ch++) {
            int mt = ch >> 2, nt = ch & 3;
            int chs = ch ^ (lane & 7);
            *(float4*)&red[base + chs * 4] = *(const float4*)acc[mt][nt];
        }
    }
    __syncthreads();
    if (kgrp == 0) {
#pragma unroll
        for (int k = 1; k < 4; k++) {
            int base = ((k - 1) * 2 + nslot) * 1024 + lane * 32;
#pragma unroll
            for (int ch = 0; ch < 8; ch++) {
                int mt = ch >> 2, nt = ch & 3;
                int chs = ch ^ (lane & 7);
                float4 v = *(const float4*)&red[base + chs * 4];
                acc[mt][nt][0] += v.x; acc[mt][nt][1] += v.y;
                acc[mt][nt][2] += v.z; acc[mt][nt][3] += v.w;
            }
        }

        // ---------------- epilogue: + xp + b_hh, tanh, store planes ----------
#pragma unroll
        for (int mt = 0; mt < 2; mt++) {
            const int row0 = mbase + mt * 16 + g;
            const int row1 = row0 + 8;
#pragma unroll
            for (int nt = 0; nt < 4; nt++) {
                const int jb = nbase + nb0 + nt * 8;
                const int col = jb + 2 * t;
                float2 bv = *(const float2*)(b_hh + col);
                float2 x0 = *(const float2*)(xp_t + (size_t)row0 * H_ + col);
                float2 x1 = *(const float2*)(xp_t + (size_t)row1 * H_ + col);

                float v0 = tanhf(acc[mt][nt][0] + x0.x + bv.x);
                float v1 = tanhf(acc[mt][nt][1] + x0.y + bv.y);
                float v2 = tanhf(acc[mt][nt][2] + x1.x + bv.x);
                float v3 = tanhf(acc[mt][nt][3] + x1.y + bv.y);

                float h0 = tf32_rna(v0), h1 = tf32_rna(v1);
                float h2 = tf32_rna(v2), h3 = tf32_rna(v3);

                // plain layout for classifier / debugging
                *(float2*)(hf_out + (size_t)row0 * H_ + col) = make_float2(v0, v1);
                *(float2*)(hf_out + (size_t)row1 * H_ + col) = make_float2(v2, v3);

                // permuted positions for next step's MMA operands
                const int p0 = jb + (((2 * t) & 3) << 1) + (t >> 1);
                const int p1 = jb + (((2 * t + 1) & 3) << 1) + (t >> 1);
                hhi_out[(size_t)row0 * H_ + p0] = h0;
                hhi_out[(size_t)row0 * H_ + p1] = h1;
                hhi_out[(size_t)row1 * H_ + p0] = h2;
                hhi_out[(size_t)row1 * H_ + p1] = h3;
                hlo_out[(size_t)row0 * H_ + p0] = tf32_rna(v0 - h0);
                hlo_out[(size_t)row0 * H_ + p1] = tf32_rna(v1 - h1);
                hlo_out[(size_t)row1 * H_ + p0] = tf32_rna(v2 - h2);
                hlo_out[(size_t)row1 * H_ + p1] = tf32_rna(v3 - h3);
            }
        }
    }
}

// ---------------------------------------------------------------------------
// Kernel 1: fused embedding gather + input projection (scalar SGEMM)
// ---------------------------------------------------------------------------
__global__ __launch_bounds__(256) void embed_proj_kernel(
    const int* __restrict__ x, const float* __restrict__ emb,
    const float* __restrict__ W_ih, const float* __restrict__ b_ih)
{
    __shared__ float As[16][132];
    __shared__ float Bs[16][132];
    __shared__ int tok_s[128];

    const int tid  = threadIdx.x;
    const int brow = blockIdx.y;
    const int bcol = blockIdx.x;

    if (tid < 128) {
        int r = brow * 128 + tid;
        int s = r / B_;
        int b = r % B_;
        tok_s[tid] = x[b * S_ + s];
    }
    __syncthreads();

    const int ty = tid >> 4;
    const int tx = tid & 15;

    float acc[8][8];
#pragma unroll
    for (int i = 0; i < 8; i++)
#pragma unroll
        for (int j = 0; j < 8; j++) acc[i][j] = 0.f;

    for (int k0 = 0; k0 < E_; k0 += 16) {
#pragma unroll
        for (int l = 0; l < 2; l++) {
            int vid = tid + l * 256;
            int m = vid >> 2;
            int q = vid & 3;
            float4 a = *(const float4*)(emb + (size_t)tok_s[m] * E_ + k0 + q * 4);
            As[q * 4 + 0][m] = a.x; As[q * 4 + 1][m] = a.y;
            As[q * 4 + 2][m] = a.z; As[q * 4 + 3][m] = a.w;
            float4 w = *(const float4*)(W_ih + (size_t)(bcol * 128 + m) * E_ + k0 + q * 4);
            Bs[q * 4 + 0][m] = w.x; Bs[q * 4 + 1][m] = w.y;
            Bs[q * 4 + 2][m] = w.z; Bs[q * 4 + 3][m] = w.w;
        }
        __syncthreads();

#pragma unroll
        for (int kk = 0; kk < 16; kk++) {
            float ra[8], rb[8];
#pragma unroll
            for (int i = 0; i < 8; i++) ra[i] = As[kk][ty * 8 + i];
#pragma unroll
            for (int j = 0; j < 8; j++) rb[j] = Bs[kk][tx * 8 + j];
#pragma unroll
            for (int i = 0; i < 8; i++)
#pragma unroll
                for (int j = 0; j < 8; j++) acc[i][j] += ra[i] * rb[j];
        }
        __syncthreads();
    }

#pragma unroll
    for (int i = 0; i < 8; i++) {
        int r = brow * 128 + ty * 8 + i;
        float* dst = g_xp + (size_t)r * H_ + bcol * 128 + tx * 8;
        int colb = bcol * 128 + tx * 8;
#pragma unroll
        for (int j = 0; j < 8; j++)
            dst[j] = acc[i][j] + b_ih[colb + j];
    }
}

// ---------------------------------------------------------------------------
// Classifier GEMM (scalar, tiny)
// ---------------------------------------------------------------------------
__global__ __launch_bounds__(256) void gemm_clf(
    const float* __restrict__ A, const float* __restrict__ W,
    const float* __restrict__ bias, float* __restrict__ C, int N, int K)
{
    __shared__ float As[16][36];
    __shared__ float Bs[16][68];

    const int tid = threadIdx.x;
    const int rowBase = blockIdx.y * 32;
    const int colBase = blockIdx.x * 64;
    const int tr = tid >> 5;
    const int tc = tid & 31;

    float acc[4][2];
#pragma unroll
    for (int i = 0; i < 4; i++) { acc[i][0] = 0.f; acc[i][1] = 0.f; }

    for (int k0 = 0; k0 < K; k0 += 16) {
        if (tid < 128) {
            int m = tid >> 2, q = tid & 3;
            float4 a = *(const float4*)(A + (size_t)(rowBase + m) * K + k0 + q * 4);
            As[q * 4 + 0][m] = a.x; As[q * 4 + 1][m] = a.y;
            As[q * 4 + 2][m] = a.z; As[q * 4 + 3][m] = a.w;
        }
        {
            int n = tid >> 2, q = tid & 3;
            float4 w = *(const float4*)(W + (size_t)(colBase + n) * K + k0 + q * 4);
            Bs[q * 4 + 0][n] = w.x; Bs[q * 4 + 1][n] = w.y;
            Bs[q * 4 + 2][n] = w.z; Bs[q * 4 + 3][n] = w.w;
        }
        __syncthreads();

#pragma unroll
        for (int kk = 0; kk < 16; kk++) {
            float ra[4], rb[2];
#pragma unroll
            for (int i = 0; i < 4; i++) ra[i] = As[kk][tr * 4 + i];
            rb[0] = Bs[kk][tc * 2 + 0];
            rb[1] = Bs[kk][tc * 2 + 1];
#pragma unroll
            for (int i = 0; i < 4; i++) {
                acc[i][0] += ra[i] * rb[0];
                acc[i][1] += ra[i] * rb[1];
            }
        }
        __syncthreads();
    }

#pragma unroll
    for (int i = 0; i < 4; i++) {
        int row = rowBase + tr * 4 + i;
#pragma unroll
        for (int j = 0; j < 2; j++) {
            int col = colBase + tc * 2 + j;
            C[(size_t)row * N + col] = acc[i][j] + bias[col];
        }
    }
}

// ---------------------------------------------------------------------------
// Init kernels
// ---------------------------------------------------------------------------
__global__ void zero_h_kernel() {
    int i = blockIdx.x * blockDim.x + threadIdx.x;
    if (i < B_ * H_) {
        g_h[0][i] = 0.f;
        g_hsplit[0][i] = 0.f;
        g_hsplit[1][i] = 0.f;
    }
}

__global__ void wsplit_kernel(const float* __restrict__ W) {
    int i = blockIdx.x * blockDim.x + threadIdx.x;
    if (i < H_ * H_) {
        int row = i >> 10;
        int col = i & 1023;
        int j = col & 7;
        int p = (col & ~7) | ((j & 3) << 1) | (j >> 2);   // k-pair permutation
        float w = W[i];
        float hi = tf32_rna(w);
        g_wsplit[0][(size_t)row * H_ + p] = hi;
        g_wsplit[1][(size_t)row * H_ + p] = tf32_rna(w - hi);
    }
}

// ---------------------------------------------------------------------------
extern "C" void kernel_launch(void* const* d_in, const int* in_sizes, int n_in,
                              void* d_out, int out_size)
{
    const int*   x     = (const int*)d_in[0];
    const float* emb   = (const float*)d_in[1];
    const float* W_ih  = (const float*)d_in[2];
    const float* b_ih  = (const float*)d_in[3];
    const float* W_hh  = (const float*)d_in[4];
    const float* b_hh  = (const float*)d_in[5];
    const float* W_clf = (const float*)d_in[6];
    const float* b_clf = (const float*)d_in[7];
    float*       out   = (float*)d_out;

    float *xp = nullptr, *hb = nullptr, *hs = nullptr, *ws = nullptr;
    cudaGetSymbolAddress((void**)&xp, g_xp);
    cudaGetSymbolAddress((void**)&hb, g_h);
    cudaGetSymbolAddress((void**)&hs, g_hsplit);
    cudaGetSymbolAddress((void**)&ws, g_wsplit);

    static bool attrSet = false;
    if (!attrSet) {
        cudaFuncSetAttribute(rnn_step_kernel,
                             cudaFuncAttributeMaxDynamicSharedMemorySize, STEP_SMEM);
        attrSet = true;
    }

    // --- init: h0 = 0, split W_hh into permuted hi/lo tf32 planes ---
    zero_h_kernel<<<(B_ * H_ + 255) / 256, 256>>>();
    wsplit_kernel<<<(H_ * H_ + 255) / 256, 256>>>(W_hh);

    // --- xp[s,b,h] = emb[x[b,s]] @ W_ih^T + b_ih ---
    embed_proj_kernel<<<dim3(H_ / 128, (B_ * S_) / 128), 256>>>(x, emb, W_ih, b_ih);

    // --- scan: h_{t+1} = tanh(h_t @ W_hh^T + xp_t + b_hh) ---
    const float* whi = ws;
    const float* wlo = ws + (size_t)H_ * H_;
    for (int s = 0; s < S_; s++) {
        int in_buf = s & 1;
        int out_buf = (s + 1) & 1;
        const float* xpt = xp + (size_t)s * B_ * H_;
        rnn_step_kernel<<<dim3(16, 8), 256, STEP_SMEM>>>(
            hs + (size_t)(in_buf * 2) * B_ * H_,
            hs + (size_t)(in_buf * 2 + 1) * B_ * H_,
            whi, wlo, xpt, b_hh,
            hb + (size_t)out_buf * B_ * H_,
            hs + (size_t)(out_buf * 2) * B_ * H_,
            hs + (size_t)(out_buf * 2 + 1) * B_ * H_);
    }

    // --- classifier: out = h_final @ W_clf^T + b_clf (final in buffer 0) ---
    gemm_clf<<<dim3(O_ / 64, B_ / 32), 256>>>(hb, W_clf, b_clf, out, O_, H_);
}

// round 7
// speedup vs baseline: 1.4962x; 1.4948x over previous
#include <cuda_runtime.h>
#include <cuda_bf16.h>
#include <math.h>
#include <stdint.h>

#define B_ 256
#define S_ 512
#define E_ 1024
#define H_ 1024
#define O_ 512
#define NCTA 128

// ---------------------------------------------------------------------------
// Device scratch
// Z-quad layout for MMA operands (bf16 hi/lo):
//   per row: 256 16B chunks; chunk c = kb*4 + t (kb = k16 block 0..63, t = 0..3)
//   chunk = [hiPair(2t,2t+1), hiPair(2t+8,2t+9), loPair(2t,2t+1), loPair(2t+8,2t+9)]
// ---------------------------------------------------------------------------
__device__ float    g_xp[S_ * B_ * H_];     // [S,B,H] input projections (fp32)
__device__ float    g_hf[B_ * H_];          // final hidden state (fp32 plain)
__device__ uint32_t g_wz[H_ * 1024];        // W_hh Z-layout (4 MB)
__device__ uint32_t g_hz[2][B_ * 1024];     // h Z-layout, double buffered
__device__ int      g_bar;                  // grid barrier counter

// ---------------------------------------------------------------------------
// Helpers
// ---------------------------------------------------------------------------
__device__ __forceinline__ uint32_t smem_u32(const void* p) {
    uint32_t a;
    asm("{ .reg .u64 t; cvta.to.shared.u64 t, %1; cvt.u32.u64 %0, t; }" : "=r"(a) : "l"(p));
    return a;
}
__device__ __forceinline__ uint32_t pack_bf16(float lo, float hi) {
    uint32_t u; asm("cvt.rn.bf16x2.f32 %0, %1, %2;" : "=r"(u) : "f"(hi), "f"(lo));
    return u;   // low 16 bits = lo arg, high = hi arg
}

#define CP_ASYNC16(dst, src) \
    asm volatile("cp.async.cg.shared.global [%0], [%1], 16;" :: "r"(dst), "l"(src))
#define CP_COMMIT() asm volatile("cp.async.commit_group;" ::: "memory")
#define CP_WAIT0()  asm volatile("cp.async.wait_group 0;" ::: "memory")
#define CP_WAIT1()  asm volatile("cp.async.wait_group 1;" ::: "memory")
#define CP_WAIT2()  asm volatile("cp.async.wait_group 2;" ::: "memory")

// D += A*B  (m16n8k16 bf16, row.col, fp32 accum)
__device__ __forceinline__ void mma_bf16(float* c,
    uint32_t a0, uint32_t a1, uint32_t a2, uint32_t a3, uint32_t b0, uint32_t b1)
{
    asm volatile(
        "mma.sync.aligned.m16n8k16.row.col.f32.bf16.bf16.f32 "
        "{%0,%1,%2,%3}, {%4,%5,%6,%7}, {%8,%9}, {%0,%1,%2,%3};"
        : "+f"(c[0]), "+f"(c[1]), "+f"(c[2]), "+f"(c[3])
        : "r"(a0), "r"(a1), "r"(a2), "r"(a3), "r"(b0), "r"(b1));
}

// ---------------------------------------------------------------------------
// Persistent scan kernel.
// 128 CTAs x 256 thr. CTA tile M=64 (batch) x N=32 (h cols).
// Warp = (mslot in 2) x (kgrp in 4); per warp: m32 x n32 over K/4.
// SMEM: [0,128K) resident W slice; [128K,128K+96K) 3-stage h pipeline.
// ---------------------------------------------------------------------------
#define W_BYTES   131072
#define STG_BYTES 32768
#define SCAN_SMEM (W_BYTES + 3 * STG_BYTES)   // 229376
#define NIT 8

__global__ __launch_bounds__(256, 1) void rnn_scan_kernel(const float* __restrict__ b_hh)
{
    extern __shared__ char sm[];
    char* smW = sm;
    char* smA = sm + W_BYTES;
    const uint32_t smWu = smem_u32(smW);
    const uint32_t smAu = smem_u32(smA);

    const int tid = threadIdx.x;
    const int wid = tid >> 5, lane = tid & 31;
    const int g = lane >> 2, t = lane & 3;
    const int mslot = wid & 1, kgrp = wid >> 1;

    const int cta = blockIdx.x;
    const int nblk = cta & 31, mblk = cta >> 5;
    const int nbase = nblk * 32, mbase = mblk * 64;

    // ---- resident W slice load (once) ----
    for (int j = 0; j < 32; j++) {
        int idx = tid + j * 256;
        int row = idx >> 8, cc = idx & 255;
        uint32_t dst = smWu + row * 4096 + ((cc ^ ((row & 1) << 2)) << 4);
        CP_ASYNC16(dst, g_wz + (((size_t)(nbase + row)) << 10) + (cc << 2));
    }
    CP_COMMIT(); CP_WAIT0();
    __syncthreads();

    // ---- thread-constant operand offsets ----
    const int wk0 = t ^ ((g & 1) << 2);        // k16=0 chunk perm
    const int wk1 = (4 + t) ^ ((g & 1) << 2);  // k16=1
    const char* Ap = smA + (mslot * 32 + g) * 512 + kgrp * 128;
    const char* Wp = smW + g * 4096 + kgrp * 128;

    // ---- epilogue thread-constant mapping ----
    const int erow = tid >> 2;                  // 0..63
    const int pb = (tid & 3) * 4;               // pair base 0,4,8,12
    const int mslot_r = erow >> 5, mt_r = (erow >> 4) & 1;
    const int half_r = (erow >> 3) & 1, g_r = erow & 7;
    const size_t growbase = ((size_t)(mbase + erow)) << 10;

    float* red = (float*)smA;

#pragma unroll 1
    for (int s = 0; s < S_; s++) {
        const uint32_t* hzin = g_hz[s & 1];
        uint32_t* hzout = g_hz[(s + 1) & 1];
        const float* xp_t = g_xp + (size_t)s * (B_ * H_);

        // prefill stages 0,1
#pragma unroll
        for (int st = 0; st < 2; st++) {
#pragma unroll
            for (int j = 0; j < 8; j++) {
                int idx = tid + j * 256;
                int row = idx >> 5, cc = idx & 31;
                uint32_t dst = smAu + st * STG_BYTES + row * 512 +
                               ((cc ^ ((row & 1) << 2)) << 4);
                CP_ASYNC16(dst, hzin + (((size_t)(mbase + row)) << 10) +
                                ((st * 32 + cc) << 2));
            }
            CP_COMMIT();
        }

        float acc[2][4][4];
#pragma unroll
        for (int mt = 0; mt < 2; mt++)
#pragma unroll
            for (int nt = 0; nt < 4; nt++)
#pragma unroll
                for (int i = 0; i < 4; i++) acc[mt][nt][i] = 0.f;

        for (int it = 0; it < NIT; it++) {
            if (it + 2 < NIT) {
                int st = (it + 2) % 3;
#pragma unroll
                for (int j = 0; j < 8; j++) {
                    int idx = tid + j * 256;
                    int row = idx >> 5, cc = idx & 31;
                    uint32_t dst = smAu + st * STG_BYTES + row * 512 +
                                   ((cc ^ ((row & 1) << 2)) << 4);
                    CP_ASYNC16(dst, hzin + (((size_t)(mbase + row)) << 10) +
                                    (((it + 2) * 32 + cc) << 2));
                }
                CP_COMMIT();
                CP_WAIT2();
            } else if (it + 1 < NIT) {
                CP_WAIT1();
            } else {
                CP_WAIT0();
            }
            __syncthreads();

            const int stOff = (it % 3) * STG_BYTES;
#pragma unroll
            for (int k16 = 0; k16 < 2; k16++) {
                const int wkk = (k16 ? wk1 : wk0) * 16;
                uint4 aq[2][2];
#pragma unroll
                for (int mt = 0; mt < 2; mt++)
#pragma unroll
                    for (int hf = 0; hf < 2; hf++)
                        aq[mt][hf] = *(const uint4*)(Ap + stOff +
                                     (mt * 16 + hf * 8) * 512 + wkk);
                uint4 wq[4];
#pragma unroll
                for (int nt = 0; nt < 4; nt++)
                    wq[nt] = *(const uint4*)(Wp + nt * 32768 + it * 512 + wkk);

#pragma unroll
                for (int nt = 0; nt < 4; nt++)
#pragma unroll
                    for (int mt = 0; mt < 2; mt++)
                        mma_bf16(acc[mt][nt], aq[mt][0].x, aq[mt][1].x,
                                 aq[mt][0].y, aq[mt][1].y, wq[nt].x, wq[nt].y);
#pragma unroll
                for (int nt = 0; nt < 4; nt++)
#pragma unroll
                    for (int mt = 0; mt < 2; mt++)
                        mma_bf16(acc[mt][nt], aq[mt][0].x, aq[mt][1].x,
                                 aq[mt][0].y, aq[mt][1].y, wq[nt].z, wq[nt].w);
#pragma unroll
                for (int nt = 0; nt < 4; nt++)
#pragma unroll
                    for (int mt = 0; mt < 2; mt++)
                        mma_bf16(acc[mt][nt], aq[mt][0].z, aq[mt][1].z,
                                 aq[mt][0].w, aq[mt][1].w, wq[nt].x, wq[nt].y);
            }
            __syncthreads();
        }

        // ---- K-split reduction: all warps dump accs to smem ----
        {
            float* wr = red + wid * 1024 + lane * 32;
#pragma unroll
            for (int combo = 0; combo < 8; combo++) {
                int mt = combo >> 2, nt = combo & 3;
                *(float4*)(wr + ((combo ^ (lane & 7)) << 2)) =
                    *(const float4*)acc[mt][nt];
            }
        }
        __syncthreads();

        // ---- epilogue: each thread 4 col-pairs of its row ----
        {
            const int e = half_r * 2;
#pragma unroll
            for (int i = 0; i < 4; i++) {
                int p = pb + i;
                int nt_r = p >> 2, t_r = p & 3;
                int lane_r = g_r * 4 + t_r;
                int combo = mt_r * 4 + nt_r;
                int off = lane_r * 32 + ((combo ^ (lane_r & 7)) << 2) + e;
                float s0 = 0.f, s1 = 0.f;
#pragma unroll
                for (int k = 0; k < 4; k++) {
                    const float* rr = red + (k * 2 + mslot_r) * 1024 + off;
                    s0 += rr[0]; s1 += rr[1];
                }
                int col = nbase + 2 * p;
                float2 xv = *(const float2*)(xp_t + growbase + col);
                float2 bv = *(const float2*)(b_hh + col);
                float v0 = tanhf(s0 + xv.x + bv.x);
                float v1 = tanhf(s1 + xv.y + bv.y);

                uint32_t hiU = pack_bf16(v0, v1);
                float r0 = v0 - __uint_as_float(hiU << 16);
                float r1 = v1 - __uint_as_float(hiU & 0xFFFF0000u);
                uint32_t loU = pack_bf16(r0, r1);

                int kb = col >> 4;
                int pp = (col >> 1) & 7;
                uint32_t* dst = hzout + growbase + kb * 16 + (pp & 3) * 4;
                dst[pp >> 2] = hiU;
                dst[(pp >> 2) + 2] = loU;

                if (s == S_ - 1)
                    *(float2*)(g_hf + growbase + col) = make_float2(v0, v1);
            }
        }

        // ---- grid barrier ----
        __syncthreads();
        if (tid == 0) {
            __threadfence();
            atomicAdd(&g_bar, 1);
            int target = NCTA * (s + 1);
            while (*(volatile int*)&g_bar < target) __nanosleep(32);
            __threadfence();
        }
        __syncthreads();
    }
}

// ---------------------------------------------------------------------------
// Kernel 1: fused embedding gather + input projection (scalar SGEMM)
// ---------------------------------------------------------------------------
__global__ __launch_bounds__(256) void embed_proj_kernel(
    const int* __restrict__ x, const float* __restrict__ emb,
    const float* __restrict__ W_ih, const float* __restrict__ b_ih)
{
    __shared__ float As[16][132];
    __shared__ float Bs[16][132];
    __shared__ int tok_s[128];

    const int tid  = threadIdx.x;
    const int brow = blockIdx.y;
    const int bcol = blockIdx.x;

    if (tid < 128) {
        int r = brow * 128 + tid;
        int s = r / B_;
        int b = r % B_;
        tok_s[tid] = x[b * S_ + s];
    }
    __syncthreads();

    const int ty = tid >> 4;
    const int tx = tid & 15;

    float acc[8][8];
#pragma unroll
    for (int i = 0; i < 8; i++)
#pragma unroll
        for (int j = 0; j < 8; j++) acc[i][j] = 0.f;

    for (int k0 = 0; k0 < E_; k0 += 16) {
#pragma unroll
        for (int l = 0; l < 2; l++) {
            int vid = tid + l * 256;
            int m = vid >> 2;
            int q = vid & 3;
            float4 a = *(const float4*)(emb + (size_t)tok_s[m] * E_ + k0 + q * 4);
            As[q * 4 + 0][m] = a.x; As[q * 4 + 1][m] = a.y;
            As[q * 4 + 2][m] = a.z; As[q * 4 + 3][m] = a.w;
            float4 w = *(const float4*)(W_ih + (size_t)(bcol * 128 + m) * E_ + k0 + q * 4);
            Bs[q * 4 + 0][m] = w.x; Bs[q * 4 + 1][m] = w.y;
            Bs[q * 4 + 2][m] = w.z; Bs[q * 4 + 3][m] = w.w;
        }
        __syncthreads();

#pragma unroll
        for (int kk = 0; kk < 16; kk++) {
            float ra[8], rb[8];
#pragma unroll
            for (int i = 0; i < 8; i++) ra[i] = As[kk][ty * 8 + i];
#pragma unroll
            for (int j = 0; j < 8; j++) rb[j] = Bs[kk][tx * 8 + j];
#pragma unroll
            for (int i = 0; i < 8; i++)
#pragma unroll
                for (int j = 0; j < 8; j++) acc[i][j] += ra[i] * rb[j];
        }
        __syncthreads();
    }

#pragma unroll
    for (int i = 0; i < 8; i++) {
        int r = brow * 128 + ty * 8 + i;
        float* dst = g_xp + (size_t)r * H_ + bcol * 128 + tx * 8;
        int colb = bcol * 128 + tx * 8;
#pragma unroll
        for (int j = 0; j < 8; j++)
            dst[j] = acc[i][j] + b_ih[colb + j];
    }
}

// ---------------------------------------------------------------------------
// Classifier GEMM (scalar, tiny)
// ---------------------------------------------------------------------------
__global__ __launch_bounds__(256) void gemm_clf(
    const float* __restrict__ A, const float* __restrict__ W,
    const float* __restrict__ bias, float* __restrict__ C, int N, int K)
{
    __shared__ float As[16][36];
    __shared__ float Bs[16][68];

    const int tid = threadIdx.x;
    const int rowBase = blockIdx.y * 32;
    const int colBase = blockIdx.x * 64;
    const int tr = tid >> 5;
    const int tc = tid & 31;

    float acc[4][2];
#pragma unroll
    for (int i = 0; i < 4; i++) { acc[i][0] = 0.f; acc[i][1] = 0.f; }

    for (int k0 = 0; k0 < K; k0 += 16) {
        if (tid < 128) {
            int m = tid >> 2, q = tid & 3;
            float4 a = *(const float4*)(A + (size_t)(rowBase + m) * K + k0 + q * 4);
            As[q * 4 + 0][m] = a.x; As[q * 4 + 1][m] = a.y;
            As[q * 4 + 2][m] = a.z; As[q * 4 + 3][m] = a.w;
        }
        {
            int n = tid >> 2, q = tid & 3;
            float4 w = *(const float4*)(W + (size_t)(colBase + n) * K + k0 + q * 4);
            Bs[q * 4 + 0][n] = w.x; Bs[q * 4 + 1][n] = w.y;
            Bs[q * 4 + 2][n] = w.z; Bs[q * 4 + 3][n] = w.w;
        }
        __syncthreads();

#pragma unroll
        for (int kk = 0; kk < 16; kk++) {
            float ra[4], rb[2];
#pragma unroll
            for (int i = 0; i < 4; i++) ra[i] = As[kk][tr * 4 + i];
            rb[0] = Bs[kk][tc * 2 + 0];
            rb[1] = Bs[kk][tc * 2 + 1];
#pragma unroll
            for (int i = 0; i < 4; i++) {
                acc[i][0] += ra[i] * rb[0];
                acc[i][1] += ra[i] * rb[1];
            }
        }
        __syncthreads();
    }

#pragma unroll
    for (int i = 0; i < 4; i++) {
        int row = rowBase + tr * 4 + i;
#pragma unroll
        for (int j = 0; j < 2; j++) {
            int col = colBase + tc * 2 + j;
            C[(size_t)row * N + col] = acc[i][j] + bias[col];
        }
    }
}

// ---------------------------------------------------------------------------
// Init kernels
// ---------------------------------------------------------------------------
__global__ void zero_init_kernel() {
    int i = blockIdx.x * blockDim.x + threadIdx.x;
    if (i < B_ * 1024) g_hz[0][i] = 0u;
    if (i == 0) g_bar = 0;
}

// W_hh -> Z-layout bf16 hi/lo planes
__global__ void wsplit_kernel(const float* __restrict__ W) {
    int idx = blockIdx.x * blockDim.x + threadIdx.x;
    if (idx >= H_ * 512) return;
    int n = idx >> 9, p = idx & 511;
    int col = 2 * p;
    float w0 = W[(size_t)n * H_ + col];
    float w1 = W[(size_t)n * H_ + col + 1];
    uint32_t hiU = pack_bf16(w0, w1);
    float r0 = w0 - __uint_as_float(hiU << 16);
    float r1 = w1 - __uint_as_float(hiU & 0xFFFF0000u);
    uint32_t loU = pack_bf16(r0, r1);
    int kb = col >> 4;
    int pp = (col >> 1) & 7;
    uint32_t* dst = g_wz + ((size_t)n << 10) + kb * 16 + (pp & 3) * 4;
    dst[pp >> 2] = hiU;
    dst[(pp >> 2) + 2] = loU;
}

// ---------------------------------------------------------------------------
extern "C" void kernel_launch(void* const* d_in, const int* in_sizes, int n_in,
                              void* d_out, int out_size)
{
    const int*   x     = (const int*)d_in[0];
    const float* emb   = (const float*)d_in[1];
    const float* W_ih  = (const float*)d_in[2];
    const float* b_ih  = (const float*)d_in[3];
    const float* W_hh  = (const float*)d_in[4];
    const float* b_hh  = (const float*)d_in[5];
    const float* W_clf = (const float*)d_in[6];
    const float* b_clf = (const float*)d_in[7];
    float*       out   = (float*)d_out;

    float* hf = nullptr;
    cudaGetSymbolAddress((void**)&hf, g_hf);

    static bool attrSet = false;
    if (!attrSet) {
        cudaFuncSetAttribute(rnn_scan_kernel,
                             cudaFuncAttributeMaxDynamicSharedMemorySize, SCAN_SMEM);
        attrSet = true;
    }

    // init: h0 = 0, barrier = 0, W_hh -> bf16 Z planes
    zero_init_kernel<<<(B_ * 1024 + 255) / 256, 256>>>();
    wsplit_kernel<<<(H_ * 512 + 255) / 256, 256>>>(W_hh);

    // xp[s,b,h] = emb[x[b,s]] @ W_ih^T + b_ih
    embed_proj_kernel<<<dim3(H_ / 128, (B_ * S_) / 128), 256>>>(x, emb, W_ih, b_ih);

    // full scan in one persistent kernel
    rnn_scan_kernel<<<NCTA, 256, SCAN_SMEM>>>(b_hh);

    // classifier
    gemm_clf<<<dim3(O_ / 64, B_ / 32), 256>>>(hf, W_clf, b_clf, out, O_, H_);
}

// round 8
// speedup vs baseline: 2.1676x; 1.4487x over previous
#include <cuda_runtime.h>
#include <cuda_bf16.h>
#include <math.h>
#include <stdint.h>

#define B_ 256
#define S_ 512
#define V_ 32000
#define E_ 1024
#define H_ 1024
#define O_ 512
#define NCTA 128

// ---------------------------------------------------------------------------
// Device scratch
// Z-quad layout (bf16 hi/lo) per row of K=1024:
//   1024 u32 per row; chunk c = kb*16 + t*4 u32s (kb = k16 block, t = 0..3):
//   [hiPair(2t,2t+1), hiPair(2t+8,2t+9), loPair(2t,2t+1), loPair(2t+8,2t+9)]
// ---------------------------------------------------------------------------
__device__ float    g_xp[S_ * B_ * H_];     // [S,B,H] input projections (fp32)
__device__ float    g_hf[B_ * H_];          // final hidden state (fp32 plain)
__device__ uint32_t g_wz[H_ * 1024];        // W_hh  Z-layout (4 MB)
__device__ uint32_t g_wihz[H_ * 1024];      // W_ih  Z-layout (4 MB)
__device__ uint32_t g_embz[(size_t)V_ * 1024];  // emb Z-layout (128 MB)
__device__ uint32_t g_hz[2][B_ * 1024];     // h Z-layout, double buffered
__device__ int      g_bar;                  // grid barrier counter

// ---------------------------------------------------------------------------
// Helpers
// ---------------------------------------------------------------------------
__device__ __forceinline__ uint32_t smem_u32(const void* p) {
    uint32_t a;
    asm("{ .reg .u64 t; cvta.to.shared.u64 t, %1; cvt.u32.u64 %0, t; }" : "=r"(a) : "l"(p));
    return a;
}
__device__ __forceinline__ uint32_t pack_bf16(float lo, float hi) {
    uint32_t u; asm("cvt.rn.bf16x2.f32 %0, %1, %2;" : "=r"(u) : "f"(hi), "f"(lo));
    return u;
}

#define CP_ASYNC16(dst, src) \
    asm volatile("cp.async.cg.shared.global [%0], [%1], 16;" :: "r"(dst), "l"(src))
#define CP_COMMIT() asm volatile("cp.async.commit_group;" ::: "memory")
#define CP_WAIT0()  asm volatile("cp.async.wait_group 0;" ::: "memory")
#define CP_WAIT1()  asm volatile("cp.async.wait_group 1;" ::: "memory")
#define CP_WAIT2()  asm volatile("cp.async.wait_group 2;" ::: "memory")

// D += A*B  (m16n8k16 bf16, row.col, fp32 accum)
__device__ __forceinline__ void mma_bf16(float* c,
    uint32_t a0, uint32_t a1, uint32_t a2, uint32_t a3, uint32_t b0, uint32_t b1)
{
    asm volatile(
        "mma.sync.aligned.m16n8k16.row.col.f32.bf16.bf16.f32 "
        "{%0,%1,%2,%3}, {%4,%5,%6,%7}, {%8,%9}, {%0,%1,%2,%3};"
        : "+f"(c[0]), "+f"(c[1]), "+f"(c[2]), "+f"(c[3])
        : "r"(a0), "r"(a1), "r"(a2), "r"(a3), "r"(b0), "r"(b1));
}

// ---------------------------------------------------------------------------
// Persistent scan kernel (conflict-free swizzle: pos = cc ^ (row & 7)).
// 128 CTAs x 256 thr. CTA tile M=64 x N=32. Warp = (mslot in 2) x (kgrp in 4).
// ---------------------------------------------------------------------------
#define W_BYTES   131072
#define STG_BYTES 32768
#define SCAN_SMEM (W_BYTES + 3 * STG_BYTES)
#define NIT 8

__global__ __launch_bounds__(256, 1) void rnn_scan_kernel(const float* __restrict__ b_hh)
{
    extern __shared__ char sm[];
    char* smW = sm;
    char* smA = sm + W_BYTES;
    const uint32_t smWu = smem_u32(smW);
    const uint32_t smAu = smem_u32(smA);

    const int tid = threadIdx.x;
    const int wid = tid >> 5, lane = tid & 31;
    const int g = lane >> 2, t = lane & 3;
    const int mslot = wid & 1, kgrp = wid >> 1;

    const int cta = blockIdx.x;
    const int nblk = cta & 31, mblk = cta >> 5;
    const int nbase = nblk * 32, mbase = mblk * 64;

    // ---- resident W slice load (once) ----
    for (int j = 0; j < 32; j++) {
        int idx = tid + j * 256;
        int row = idx >> 8, cc = idx & 255;
        uint32_t dst = smWu + row * 4096 + ((cc ^ (row & 7)) << 4);
        CP_ASYNC16(dst, g_wz + (((size_t)(nbase + row)) << 10) + (cc << 2));
    }
    CP_COMMIT(); CP_WAIT0();
    __syncthreads();

    // ---- thread-constant operand offsets (rows ≡ g mod 8) ----
    const int wk0 = t ^ g;
    const int wk1 = (4 + t) ^ g;
    const char* Ap = smA + (mslot * 32 + g) * 512 + kgrp * 128;
    const char* Wp = smW + g * 4096 + kgrp * 128;

    // ---- epilogue thread-constant mapping ----
    const int erow = tid >> 2;
    const int pb = (tid & 3) * 4;
    const int mslot_r = erow >> 5, mt_r = (erow >> 4) & 1;
    const int half_r = (erow >> 3) & 1, g_r = erow & 7;
    const size_t growbase = ((size_t)(mbase + erow)) << 10;

    float* red = (float*)smA;

#pragma unroll 1
    for (int s = 0; s < S_; s++) {
        const uint32_t* hzin = g_hz[s & 1];
        uint32_t* hzout = g_hz[(s + 1) & 1];
        const float* xp_t = g_xp + (size_t)s * (B_ * H_);

        // prefill stages 0,1
#pragma unroll
        for (int st = 0; st < 2; st++) {
#pragma unroll
            for (int j = 0; j < 8; j++) {
                int idx = tid + j * 256;
                int row = idx >> 5, cc = idx & 31;
                uint32_t dst = smAu + st * STG_BYTES + row * 512 +
                               ((cc ^ (row & 7)) << 4);
                CP_ASYNC16(dst, hzin + (((size_t)(mbase + row)) << 10) +
                                ((st * 32 + cc) << 2));
            }
            CP_COMMIT();
        }

        float acc[2][4][4];
#pragma unroll
        for (int mt = 0; mt < 2; mt++)
#pragma unroll
            for (int nt = 0; nt < 4; nt++)
#pragma unroll
                for (int i = 0; i < 4; i++) acc[mt][nt][i] = 0.f;

        for (int it = 0; it < NIT; it++) {
            if (it + 2 < NIT) {
                int st = (it + 2) % 3;
#pragma unroll
                for (int j = 0; j < 8; j++) {
                    int idx = tid + j * 256;
                    int row = idx >> 5, cc = idx & 31;
                    uint32_t dst = smAu + st * STG_BYTES + row * 512 +
                                   ((cc ^ (row & 7)) << 4);
                    CP_ASYNC16(dst, hzin + (((size_t)(mbase + row)) << 10) +
                                    (((it + 2) * 32 + cc) << 2));
                }
                CP_COMMIT();
                CP_WAIT2();
            } else if (it + 1 < NIT) {
                CP_WAIT1();
            } else {
                CP_WAIT0();
            }
            __syncthreads();

            const int stOff = (it % 3) * STG_BYTES;
#pragma unroll
            for (int k16 = 0; k16 < 2; k16++) {
                const int wkk = (k16 ? wk1 : wk0) * 16;
                uint4 aq[2][2];
#pragma unroll
                for (int mt = 0; mt < 2; mt++)
#pragma unroll
                    for (int hf = 0; hf < 2; hf++)
                        aq[mt][hf] = *(const uint4*)(Ap + stOff +
                                     (mt * 16 + hf * 8) * 512 + wkk);
                uint4 wq[4];
#pragma unroll
                for (int nt = 0; nt < 4; nt++)
                    wq[nt] = *(const uint4*)(Wp + nt * 32768 + it * 512 + wkk);

#pragma unroll
                for (int nt = 0; nt < 4; nt++)
#pragma unroll
                    for (int mt = 0; mt < 2; mt++)
                        mma_bf16(acc[mt][nt], aq[mt][0].x, aq[mt][1].x,
                                 aq[mt][0].y, aq[mt][1].y, wq[nt].x, wq[nt].y);
#pragma unroll
                for (int nt = 0; nt < 4; nt++)
#pragma unroll
                    for (int mt = 0; mt < 2; mt++)
                        mma_bf16(acc[mt][nt], aq[mt][0].x, aq[mt][1].x,
                                 aq[mt][0].y, aq[mt][1].y, wq[nt].z, wq[nt].w);
#pragma unroll
                for (int nt = 0; nt < 4; nt++)
#pragma unroll
                    for (int mt = 0; mt < 2; mt++)
                        mma_bf16(acc[mt][nt], aq[mt][0].z, aq[mt][1].z,
                                 aq[mt][0].w, aq[mt][1].w, wq[nt].x, wq[nt].y);
            }
            __syncthreads();
        }

        // ---- K-split reduction ----
        {
            float* wr = red + wid * 1024 + lane * 32;
#pragma unroll
            for (int combo = 0; combo < 8; combo++) {
                int mt = combo >> 2, nt = combo & 3;
                *(float4*)(wr + ((combo ^ (lane & 7)) << 2)) =
                    *(const float4*)acc[mt][nt];
            }
        }
        __syncthreads();

        // ---- epilogue ----
        {
            const int e = half_r * 2;
#pragma unroll
            for (int i = 0; i < 4; i++) {
                int p = pb + i;
                int nt_r = p >> 2, t_r = p & 3;
                int lane_r = g_r * 4 + t_r;
                int combo = mt_r * 4 + nt_r;
                int off = lane_r * 32 + ((combo ^ (lane_r & 7)) << 2) + e;
                float s0 = 0.f, s1 = 0.f;
#pragma unroll
                for (int k = 0; k < 4; k++) {
                    const float* rr = red + (k * 2 + mslot_r) * 1024 + off;
                    s0 += rr[0]; s1 += rr[1];
                }
                int col = nbase + 2 * p;
                float2 xv = *(const float2*)(xp_t + growbase + col);
                float2 bv = *(const float2*)(b_hh + col);
                float v0 = tanhf(s0 + xv.x + bv.x);
                float v1 = tanhf(s1 + xv.y + bv.y);

                uint32_t hiU = pack_bf16(v0, v1);
                float r0 = v0 - __uint_as_float(hiU << 16);
                float r1 = v1 - __uint_as_float(hiU & 0xFFFF0000u);
                uint32_t loU = pack_bf16(r0, r1);

                int kb = col >> 4;
                int pp = (col >> 1) & 7;
                uint32_t* dst = hzout + growbase + kb * 16 + (pp & 3) * 4;
                dst[pp >> 2] = hiU;
                dst[(pp >> 2) + 2] = loU;

                if (s == S_ - 1)
                    *(float2*)(g_hf + growbase + col) = make_float2(v0, v1);
            }
        }

        // ---- grid barrier ----
        __syncthreads();
        if (tid == 0) {
            __threadfence();
            atomicAdd(&g_bar, 1);
            int target = NCTA * (s + 1);
            while (*(volatile int*)&g_bar < target) __nanosleep(32);
            __threadfence();
        }
        __syncthreads();
    }
}

// ---------------------------------------------------------------------------
// Projection GEMM: xp[r, h] = emb[tok(r)] @ W_ih^T + b_ih   (bf16 hi/lo x3)
// Grid (8 n, 1024 m), CTA tile M=128 x N=128, 256 thr, warp m64 x n32.
// 3-stage cp.async, BK=64 elems (A 32KB + B 32KB per stage).
// ---------------------------------------------------------------------------
#define PJ_STG 65536
#define PJ_SMEM (3 * PJ_STG)   // 196608
#define PJ_NIT 16

__global__ __launch_bounds__(256, 1) void proj_mma_kernel(
    const int* __restrict__ x, const float* __restrict__ b_ih)
{
    extern __shared__ char sm[];
    __shared__ int tok_s[128];
    const uint32_t smu = smem_u32(sm);

    const int tid = threadIdx.x;
    const int wid = tid >> 5, lane = tid & 31;
    const int g = lane >> 2, t = lane & 3;
    const int mslot = wid & 1, nslot = wid >> 1;

    const int nbase = blockIdx.x * 128;
    const int mbase = blockIdx.y * 128;

    if (tid < 128) {
        int r = mbase + tid;
        tok_s[tid] = x[(r % B_) * S_ + (r / B_)];
    }
    __syncthreads();

    // per-thread load geometry: 8 A rows + 8 B rows, fixed chunk
    const int lrow = tid >> 4;            // 0..15
    const int lcc  = tid & 15;            // 0..15
    const uint32_t lpos = (uint32_t)((lcc ^ (lrow & 7)) << 4);
    const uint32_t* asrc[8];
#pragma unroll
    for (int j = 0; j < 8; j++)
        asrc[j] = g_embz + (size_t)tok_s[lrow + 16 * j] * 1024 + lcc * 4;
    const uint32_t* bsrc = g_wihz + (size_t)(nbase + lrow) * 1024 + lcc * 4;

    float acc[4][4][4];
#pragma unroll
    for (int mt = 0; mt < 4; mt++)
#pragma unroll
        for (int nt = 0; nt < 4; nt++)
#pragma unroll
            for (int i = 0; i < 4; i++) acc[mt][nt][i] = 0.f;

    // prefill stages 0,1
#pragma unroll
    for (int st = 0; st < 2; st++) {
        uint32_t sb = smu + st * PJ_STG;
        int k0 = st * 64;
#pragma unroll
        for (int j = 0; j < 8; j++) {
            uint32_t d = (lrow + 16 * j) * 256 + lpos;
            CP_ASYNC16(sb + d, asrc[j] + k0);
            CP_ASYNC16(sb + 32768 + d, bsrc + j * 16 * 1024 + k0);
        }
        CP_COMMIT();
    }

    const char* Ab = sm + (mslot * 64 + g) * 256;
    const char* Bb = sm + 32768 + (nslot * 32 + g) * 256;

    for (int it = 0; it < PJ_NIT; it++) {
        if (it + 2 < PJ_NIT) {
            uint32_t sb = smu + ((it + 2) % 3) * PJ_STG;
            int k0 = (it + 2) * 64;
#pragma unroll
            for (int j = 0; j < 8; j++) {
                uint32_t d = (lrow + 16 * j) * 256 + lpos;
                CP_ASYNC16(sb + d, asrc[j] + k0);
                CP_ASYNC16(sb + 32768 + d, bsrc + j * 16 * 1024 + k0);
            }
            CP_COMMIT();
            CP_WAIT2();
        } else if (it + 1 < PJ_NIT) {
            CP_WAIT1();
        } else {
            CP_WAIT0();
        }
        __syncthreads();

        const int stOff = (it % 3) * PJ_STG;
#pragma unroll
        for (int kb = 0; kb < 4; kb++) {
            const int pos = ((kb * 4 + t) ^ g) << 4;
            uint4 aq[4][2];
#pragma unroll
            for (int mt = 0; mt < 4; mt++)
#pragma unroll
                for (int hf = 0; hf < 2; hf++)
                    aq[mt][hf] = *(const uint4*)(Ab + stOff +
                                 (mt * 16 + hf * 8) * 256 + pos);
            uint4 wq[4];
#pragma unroll
            for (int nt = 0; nt < 4; nt++)
                wq[nt] = *(const uint4*)(Bb + stOff + nt * 8 * 256 + pos);

#pragma unroll
            for (int nt = 0; nt < 4; nt++)
#pragma unroll
                for (int mt = 0; mt < 4; mt++)
                    mma_bf16(acc[mt][nt], aq[mt][0].x, aq[mt][1].x,
                             aq[mt][0].y, aq[mt][1].y, wq[nt].x, wq[nt].y);
#pragma unroll
            for (int nt = 0; nt < 4; nt++)
#pragma unroll
                for (int mt = 0; mt < 4; mt++)
                    mma_bf16(acc[mt][nt], aq[mt][0].x, aq[mt][1].x,
                             aq[mt][0].y, aq[mt][1].y, wq[nt].z, wq[nt].w);
#pragma unroll
            for (int nt = 0; nt < 4; nt++)
#pragma unroll
                for (int mt = 0; mt < 4; mt++)
                    mma_bf16(acc[mt][nt], aq[mt][0].z, aq[mt][1].z,
                             aq[mt][0].w, aq[mt][1].w, wq[nt].x, wq[nt].y);
        }
        __syncthreads();
    }

    // epilogue: + b_ih, store fp32 xp
    float2 bv[4];
#pragma unroll
    for (int nt = 0; nt < 4; nt++)
        bv[nt] = *(const float2*)(b_ih + nbase + nslot * 32 + nt * 8 + 2 * t);

#pragma unroll
    for (int mt = 0; mt < 4; mt++) {
        const size_t r0 = (size_t)(mbase + mslot * 64 + mt * 16 + g) * H_;
        const size_t r1 = r0 + 8 * H_;
#pragma unroll
        for (int nt = 0; nt < 4; nt++) {
            const int col = nbase + nslot * 32 + nt * 8 + 2 * t;
            *(float2*)(g_xp + r0 + col) =
                make_float2(acc[mt][nt][0] + bv[nt].x, acc[mt][nt][1] + bv[nt].y);
            *(float2*)(g_xp + r1 + col) =
                make_float2(acc[mt][nt][2] + bv[nt].x, acc[mt][nt][3] + bv[nt].y);
        }
    }
}

// ---------------------------------------------------------------------------
// Classifier GEMM (scalar, tiny)
// ---------------------------------------------------------------------------
__global__ __launch_bounds__(256) void gemm_clf(
    const float* __restrict__ A, const float* __restrict__ W,
    const float* __restrict__ bias, float* __restrict__ C, int N, int K)
{
    __shared__ float As[16][36];
    __shared__ float Bs[16][68];

    const int tid = threadIdx.x;
    const int rowBase = blockIdx.y * 32;
    const int colBase = blockIdx.x * 64;
    const int tr = tid >> 5;
    const int tc = tid & 31;

    float acc[4][2];
#pragma unroll
    for (int i = 0; i < 4; i++) { acc[i][0] = 0.f; acc[i][1] = 0.f; }

    for (int k0 = 0; k0 < K; k0 += 16) {
        if (tid < 128) {
            int m = tid >> 2, q = tid & 3;
            float4 a = *(const float4*)(A + (size_t)(rowBase + m) * K + k0 + q * 4);
            As[q * 4 + 0][m] = a.x; As[q * 4 + 1][m] = a.y;
            As[q * 4 + 2][m] = a.z; As[q * 4 + 3][m] = a.w;
        }
        {
            int n = tid >> 2, q = tid & 3;
            float4 w = *(const float4*)(W + (size_t)(colBase + n) * K + k0 + q * 4);
            Bs[q * 4 + 0][n] = w.x; Bs[q * 4 + 1][n] = w.y;
            Bs[q * 4 + 2][n] = w.z; Bs[q * 4 + 3][n] = w.w;
        }
        __syncthreads();

#pragma unroll
        for (int kk = 0; kk < 16; kk++) {
            float ra[4], rb[2];
#pragma unroll
            for (int i = 0; i < 4; i++) ra[i] = As[kk][tr * 4 + i];
            rb[0] = Bs[kk][tc * 2 + 0];
            rb[1] = Bs[kk][tc * 2 + 1];
#pragma unroll
            for (int i = 0; i < 4; i++) {
                acc[i][0] += ra[i] * rb[0];
                acc[i][1] += ra[i] * rb[1];
            }
        }
        __syncthreads();
    }

#pragma unroll
    for (int i = 0; i < 4; i++) {
        int row = rowBase + tr * 4 + i;
#pragma unroll
        for (int j = 0; j < 2; j++) {
            int col = colBase + tc * 2 + j;
            C[(size_t)row * N + col] = acc[i][j] + bias[col];
        }
    }
}

// ---------------------------------------------------------------------------
// Init kernels
// ---------------------------------------------------------------------------
__global__ void zero_init_kernel() {
    int i = blockIdx.x * blockDim.x + threadIdx.x;
    if (i < B_ * 1024) g_hz[0][i] = 0u;
    if (i == 0) g_bar = 0;
}

// fp32 [rows, 1024] -> Z-layout bf16 hi/lo
__global__ void split_kernel(const float* __restrict__ W, uint32_t* __restrict__ dst,
                             int rows)
{
    int idx = blockIdx.x * blockDim.x + threadIdx.x;
    if (idx >= rows * 512) return;
    int n = idx >> 9, p = idx & 511;
    int col = 2 * p;
    float w0 = W[(size_t)n * 1024 + col];
    float w1 = W[(size_t)n * 1024 + col + 1];
    uint32_t hiU = pack_bf16(w0, w1);
    float r0 = w0 - __uint_as_float(hiU << 16);
    float r1 = w1 - __uint_as_float(hiU & 0xFFFF0000u);
    uint32_t loU = pack_bf16(r0, r1);
    int kb = col >> 4;
    int pp = (col >> 1) & 7;
    uint32_t* d = dst + ((size_t)n << 10) + kb * 16 + (pp & 3) * 4;
    d[pp >> 2] = hiU;
    d[(pp >> 2) + 2] = loU;
}

// ---------------------------------------------------------------------------
extern "C" void kernel_launch(void* const* d_in, const int* in_sizes, int n_in,
                              void* d_out, int out_size)
{
    const int*   x     = (const int*)d_in[0];
    const float* emb   = (const float*)d_in[1];
    const float* W_ih  = (const float*)d_in[2];
    const float* b_ih  = (const float*)d_in[3];
    const float* W_hh  = (const float*)d_in[4];
    const float* b_hh  = (const float*)d_in[5];
    const float* W_clf = (const float*)d_in[6];
    const float* b_clf = (const float*)d_in[7];
    float*       out   = (float*)d_out;

    float* hf = nullptr;
    uint32_t *wz = nullptr, *wihz = nullptr, *embz = nullptr;
    cudaGetSymbolAddress((void**)&hf, g_hf);
    cudaGetSymbolAddress((void**)&wz, g_wz);
    cudaGetSymbolAddress((void**)&wihz, g_wihz);
    cudaGetSymbolAddress((void**)&embz, g_embz);

    static bool attrSet = false;
    if (!attrSet) {
        cudaFuncSetAttribute(rnn_scan_kernel,
                             cudaFuncAttributeMaxDynamicSharedMemorySize, SCAN_SMEM);
        cudaFuncSetAttribute(proj_mma_kernel,
                             cudaFuncAttributeMaxDynamicSharedMemorySize, PJ_SMEM);
        attrSet = true;
    }

    // init + conversions
    zero_init_kernel<<<(B_ * 1024 + 255) / 256, 256>>>();
    split_kernel<<<(H_ * 512 + 255) / 256, 256>>>(W_hh, wz, H_);
    split_kernel<<<(H_ * 512 + 255) / 256, 256>>>(W_ih, wihz, H_);
    split_kernel<<<(V_ * 512 + 255) / 256, 256>>>(emb, embz, V_);

    // projection (tensor cores)
    proj_mma_kernel<<<dim3(8, 1024), 256, PJ_SMEM>>>(x, b_ih);

    // full scan in one persistent kernel
    rnn_scan_kernel<<<NCTA, 256, SCAN_SMEM>>>(b_hh);

    // classifier
    gemm_clf<<<dim3(O_ / 64, B_ / 32), 256>>>(hf, W_clf, b_clf, out, O_, H_);
}